// round 4
// baseline (speedup 1.0000x reference)
#include <cuda_runtime.h>
#include <cuda_bf16.h>

// RecSysGNN (LightGCN, 3 layers) on GB300.
// R4: edge dtype (int32 vs int64) detected on-device (JAX x64-off likely made
// edge_index int32; reading it as int64 caused the 717 address-space traps).
// All data-derived indices are bounds-guarded so bad decoding can never trap.
// CSR-by-dst build once per launch, then 3 node-parallel SpMM passes
// (one warp per dst node, float2 slice per lane), no atomics in hot loop.

#define NMAX 200000
#define EMAX 4000000
#define DIM  64

__device__ int   g_is64;
__device__ int   g_counts[NMAX];
__device__ int   g_cursor[NMAX];
__device__ int   g_offs[NMAX];
__device__ float g_dinv[NMAX];
__device__ int   g_bsums[1024];
__device__ __align__(16) int   g_csr_src[EMAX];
__device__ __align__(16) float g_csr_norm[EMAX];
__device__ __align__(16) float g_embA[(size_t)NMAX * DIM];
__device__ __align__(16) float g_embB[(size_t)NMAX * DIM];

// ---------------------------------------------------------------------------
// Detect element width: int64 values < 2^31 have zero high (odd) words.
__global__ void k_sniff(const int* __restrict__ e) {
    __shared__ int any;
    if (threadIdx.x == 0) any = 0;
    __syncthreads();
    int local = 0;
    for (int i = threadIdx.x; i < 2048; i += blockDim.x)
        if (e[2 * i + 1] != 0) local = 1;
    if (local) any = 1;          // benign race: all writers store 1
    __syncthreads();
    if (threadIdx.x == 0) g_is64 = (any == 0) ? 1 : 0;
}

__device__ __forceinline__ int edge_at(const void* e, size_t idx, int is64) {
    if (is64) return (int)((const long long*)e)[idx];
    return ((const int*)e)[idx];
}

__global__ void k_zero(int n) {
    int i = blockIdx.x * blockDim.x + threadIdx.x;
    if (i < n) { g_counts[i] = 0; g_cursor[i] = 0; }
}

__global__ void k_count(const void* __restrict__ edges, int E, int N) {
    int i = blockIdx.x * blockDim.x + threadIdx.x;
    if (i >= E) return;
    int is64 = g_is64;
    int d = edge_at(edges, (size_t)E + i, is64);
    if ((unsigned)d < (unsigned)N) atomicAdd(&g_counts[d], 1);
}

__global__ void k_dinv(int n) {
    int i = blockIdx.x * blockDim.x + threadIdx.x;
    if (i < n) {
        int c = g_counts[i];
        g_dinv[i] = (c > 0) ? rsqrtf((float)c) : 0.0f;
    }
}

__device__ __forceinline__ int warp_iscan(int x, int lane) {
#pragma unroll
    for (int o = 1; o < 32; o <<= 1) {
        int y = __shfl_up_sync(0xffffffffu, x, o);
        if (lane >= o) x += y;
    }
    return x;
}

// exclusive scan of g_counts -> g_offs, 1024/block, block sums -> g_bsums
__global__ void k_scan1(int n) {
    int tid  = threadIdx.x;
    int gid  = blockIdx.x * 1024 + tid;
    int v    = (gid < n) ? g_counts[gid] : 0;
    int lane = tid & 31, wid = tid >> 5;
    int inc  = warp_iscan(v, lane);
    __shared__ int ws[32];
    if (lane == 31) ws[wid] = inc;
    __syncthreads();
    if (wid == 0) { int t = ws[lane]; t = warp_iscan(t, lane); ws[lane] = t; }
    __syncthreads();
    int incl = inc + (wid ? ws[wid - 1] : 0);
    if (gid < n) g_offs[gid] = incl - v;
    if (tid == 1023) g_bsums[blockIdx.x] = incl;
}

__global__ void k_scan2(int nb) {
    int tid  = threadIdx.x;
    int v    = (tid < nb) ? g_bsums[tid] : 0;
    int lane = tid & 31, wid = tid >> 5;
    int inc  = warp_iscan(v, lane);
    __shared__ int ws[32];
    if (lane == 31) ws[wid] = inc;
    __syncthreads();
    if (wid == 0) { int t = ws[lane]; t = warp_iscan(t, lane); ws[lane] = t; }
    __syncthreads();
    int incl = inc + (wid ? ws[wid - 1] : 0);
    if (tid < nb) g_bsums[tid] = incl - v;
}

__global__ void k_scan3(int n) {
    int gid = blockIdx.x * 1024 + threadIdx.x;
    if (gid < n) g_offs[gid] += g_bsums[blockIdx.x];
}

__global__ void k_scatter(const void* __restrict__ edges, int E, int N) {
    int i = blockIdx.x * blockDim.x + threadIdx.x;
    if (i >= E) return;
    int is64 = g_is64;
    int s = edge_at(edges, (size_t)i, is64);
    int d = edge_at(edges, (size_t)E + i, is64);
    if ((unsigned)s >= (unsigned)N || (unsigned)d >= (unsigned)N) return;
    int pos = g_offs[d] + atomicAdd(&g_cursor[d], 1);
    if ((unsigned)pos < (unsigned)EMAX) {
        g_csr_src[pos]  = s;
        g_csr_norm[pos] = g_dinv[s] * g_dinv[d];
    }
}

// d_out[0..N*D) = emb0 ; d_out[N*D..2ND) = running acc (init emb0)
__global__ void k_init_out(const float4* __restrict__ w, float4* __restrict__ out, int n4) {
    int i = blockIdx.x * blockDim.x + threadIdx.x;
    if (i < n4) {
        float4 v = w[i];
        out[i]      = v;
        out[i + n4] = v;
    }
}

// One warp per dst node; lane holds a float2 slice of the D=64 row.
__device__ __forceinline__ void prop_body(const float2* __restrict__ prev,
                                          float2* __restrict__ next,
                                          float2* __restrict__ acc,
                                          int N, bool last) {
    int warp = (blockIdx.x * blockDim.x + threadIdx.x) >> 5;
    int lane = threadIdx.x & 31;
    if (warp >= N) return;
    int start = g_offs[warp];
    int cnt   = g_counts[warp];
    float ax = 0.0f, ay = 0.0f;
    for (int b = 0; b < cnt; b += 32) {
        int j = b + lane;
        int s = 0; float nm = 0.0f;
        if (j < cnt) { s = g_csr_src[start + j]; nm = g_csr_norm[start + j]; }
        int m = min(32, cnt - b);
#pragma unroll 4
        for (int k = 0; k < m; k++) {
            int   ss = __shfl_sync(0xffffffffu, s, k);
            float nn = __shfl_sync(0xffffffffu, nm, k);
            float2 e = prev[ss * 32 + lane];
            ax = fmaf(nn, e.x, ax);
            ay = fmaf(nn, e.y, ay);
        }
    }
    int idx = warp * 32 + lane;
    if (!last) next[idx] = make_float2(ax, ay);
    float2 a = acc[idx];
    if (last) { a.x = (a.x + ax) * 0.25f; a.y = (a.y + ay) * 0.25f; }
    else      { a.x += ax;                a.y += ay; }
    acc[idx] = a;
}

__global__ void k_prop0(const float2* __restrict__ w2, float2* __restrict__ acc, int N) {
    prop_body(w2, (float2*)g_embA, acc, N, false);
}
__global__ void k_prop1(float2* __restrict__ acc, int N) {
    prop_body((const float2*)g_embA, (float2*)g_embB, acc, N, false);
}
__global__ void k_prop2(float2* __restrict__ acc, int N) {
    prop_body((const float2*)g_embB, (float2*)0, acc, N, true);
}

// ---------------------------------------------------------------------------
extern "C" void kernel_launch(void* const* d_in, const int* in_sizes, int n_in,
                              void* d_out, int out_size) {
    const void*  edges = d_in[0];                 // [2, E] int32 OR int64
    const float* w     = (const float*)d_in[1];   // float32 [N, D]
    int E = in_sizes[0] / 2;
    int N = in_sizes[1] / DIM;
    float* out = (float*)d_out;

    const int TB = 256;
    k_sniff <<<1, 256>>>((const int*)edges);
    k_zero  <<<(N + TB - 1) / TB, TB>>>(N);
    k_count <<<(E + TB - 1) / TB, TB>>>(edges, E, N);
    k_dinv  <<<(N + TB - 1) / TB, TB>>>(N);

    int nb = (N + 1023) / 1024;   // 196 for N=200000; fits single-block scan2
    k_scan1<<<nb, 1024>>>(N);
    k_scan2<<<1, 1024>>>(nb);
    k_scan3<<<nb, 1024>>>(N);

    k_scatter<<<(E + TB - 1) / TB, TB>>>(edges, E, N);

    int n4 = N * (DIM / 4);
    k_init_out<<<(n4 + TB - 1) / TB, TB>>>((const float4*)w, (float4*)out, n4);

    float2* acc = (float2*)(out + (size_t)N * DIM);
    int pgrid = (int)(((long long)N * 32 + TB - 1) / TB);
    k_prop0<<<pgrid, TB>>>((const float2*)w, acc, N);
    k_prop1<<<pgrid, TB>>>(acc, N);
    k_prop2<<<pgrid, TB>>>(acc, N);
}

// round 7
// speedup vs baseline: 1.2145x; 1.2145x over previous
#include <cuda_runtime.h>
#include <cuda_fp16.h>
#include <cuda_bf16.h>

// RecSysGNN (LightGCN, 3 layers) on GB300 — R6 (R5 with compile fix).
// - fp16 gather tables (halves dominant L2 gather traffic)
// - rank captured from count-phase atomic => scatter has NO atomics
// - packed 8B CSR entries {src, norm}
// - acc computed in one shot in prop2 (no acc RMW chain)

#define NMAX 200000
#define EMAX 4000000
#define DIM  64

struct __align__(8) Half4 { __half2 a, b; };

__device__ int      g_is64;
__device__ int      g_counts[NMAX];
__device__ int      g_offs[NMAX];
__device__ float    g_dinv[NMAX];
__device__ int      g_bsums[1024];
__device__ unsigned short g_rank[EMAX];
__device__ __align__(16) long long g_csr[EMAX];          // packed {int src, float norm}
__device__ __align__(16) __half g_w16[(size_t)NMAX * DIM];
__device__ __align__(16) __half g_l1h[(size_t)NMAX * DIM];
__device__ __align__(16) __half g_l2h[(size_t)NMAX * DIM];

// ---------------------------------------------------------------------------
// Detect edge dtype: int64 values < 2^31 have zero high (odd) words.
__global__ void k_sniff(const int* __restrict__ e) {
    __shared__ int any;
    if (threadIdx.x == 0) any = 0;
    __syncthreads();
    int local = 0;
    for (int i = threadIdx.x; i < 2048; i += blockDim.x)
        if (e[2 * i + 1] != 0) local = 1;
    if (local) any = 1;
    __syncthreads();
    if (threadIdx.x == 0) g_is64 = (any == 0) ? 1 : 0;
}

__device__ __forceinline__ int edge_at(const void* e, size_t idx, int is64) {
    if (is64) return (int)((const long long*)e)[idx];
    return ((const int*)e)[idx];
}

__global__ void k_zero(int n) {
    int i = blockIdx.x * blockDim.x + threadIdx.x;
    if (i < n) g_counts[i] = 0;
}

// count + capture per-edge rank within its dst bucket (from atomic return)
__global__ void k_count(const void* __restrict__ edges, int E, int N) {
    int i = blockIdx.x * blockDim.x + threadIdx.x;
    if (i >= E) return;
    int is64 = g_is64;
    int d = edge_at(edges, (size_t)E + i, is64);
    unsigned r = 0;
    if ((unsigned)d < (unsigned)N) r = (unsigned)atomicAdd(&g_counts[d], 1);
    g_rank[i] = (unsigned short)r;
}

__global__ void k_dinv(int n) {
    int i = blockIdx.x * blockDim.x + threadIdx.x;
    if (i < n) {
        int c = g_counts[i];
        g_dinv[i] = (c > 0) ? rsqrtf((float)c) : 0.0f;
    }
}

__device__ __forceinline__ int warp_iscan(int x, int lane) {
#pragma unroll
    for (int o = 1; o < 32; o <<= 1) {
        int y = __shfl_up_sync(0xffffffffu, x, o);
        if (lane >= o) x += y;
    }
    return x;
}

__global__ void k_scan1(int n) {
    int tid  = threadIdx.x;
    int gid  = blockIdx.x * 1024 + tid;
    int v    = (gid < n) ? g_counts[gid] : 0;
    int lane = tid & 31, wid = tid >> 5;
    int inc  = warp_iscan(v, lane);
    __shared__ int ws[32];
    if (lane == 31) ws[wid] = inc;
    __syncthreads();
    if (wid == 0) { int t = ws[lane]; t = warp_iscan(t, lane); ws[lane] = t; }
    __syncthreads();
    int incl = inc + (wid ? ws[wid - 1] : 0);
    if (gid < n) g_offs[gid] = incl - v;
    if (tid == 1023) g_bsums[blockIdx.x] = incl;
}

__global__ void k_scan2(int nb) {
    int tid  = threadIdx.x;
    int v    = (tid < nb) ? g_bsums[tid] : 0;
    int lane = tid & 31, wid = tid >> 5;
    int inc  = warp_iscan(v, lane);
    __shared__ int ws[32];
    if (lane == 31) ws[wid] = inc;
    __syncthreads();
    if (wid == 0) { int t = ws[lane]; t = warp_iscan(t, lane); ws[lane] = t; }
    __syncthreads();
    int incl = inc + (wid ? ws[wid - 1] : 0);
    if (tid < nb) g_bsums[tid] = incl - v;
}

__global__ void k_scan3(int n) {
    int gid = blockIdx.x * 1024 + threadIdx.x;
    if (gid < n) g_offs[gid] += g_bsums[blockIdx.x];
}

// no atomics: pos = offs[d] + rank[i]; single packed 8B store
__global__ void k_scatter(const void* __restrict__ edges, int E, int N) {
    int i = blockIdx.x * blockDim.x + threadIdx.x;
    if (i >= E) return;
    int is64 = g_is64;
    int s = edge_at(edges, (size_t)i, is64);
    int d = edge_at(edges, (size_t)E + i, is64);
    if ((unsigned)s >= (unsigned)N || (unsigned)d >= (unsigned)N) return;
    int pos = g_offs[d] + (int)g_rank[i];
    if ((unsigned)pos < (unsigned)EMAX) {
        float nm = g_dinv[s] * g_dinv[d];
        long long packed = (long long)(unsigned)s |
                           ((long long)(unsigned)__float_as_uint(nm) << 32);
        g_csr[pos] = packed;
    }
}

// out[0:ND) = emb0 copy; also build fp16 copy of w for layer-0 gathers
__global__ void k_init(const float4* __restrict__ w, float4* __restrict__ out, int n4) {
    int i = blockIdx.x * blockDim.x + threadIdx.x;
    if (i < n4) {
        float4 v = w[i];
        out[i] = v;
        Half4 h;
        h.a = __floats2half2_rn(v.x, v.y);
        h.b = __floats2half2_rn(v.z, v.w);
        ((Half4*)g_w16)[i] = h;
    }
}

// One warp per dst node; lane holds a half2 (2 dims) slice of the D=64 row.
__device__ __forceinline__ void gather_node(const __half2* __restrict__ prev,
                                            int start, int cnt, int lane,
                                            float& ax, float& ay) {
    for (int b = 0; b < cnt; b += 32) {
        int j = b + lane;
        int s = 0; float nm = 0.0f;
        if (j < cnt) {
            long long p = g_csr[start + j];
            s  = (int)(unsigned)(p & 0xffffffffLL);
            nm = __uint_as_float((unsigned)(p >> 32));
        }
        int m = min(32, cnt - b);
#pragma unroll 4
        for (int k = 0; k < m; k++) {
            int   ss = __shfl_sync(0xffffffffu, s, k);
            float nn = __shfl_sync(0xffffffffu, nm, k);
            float2 e = __half22float2(prev[ss * 32 + lane]);
            ax = fmaf(nn, e.x, ax);
            ay = fmaf(nn, e.y, ay);
        }
    }
}

__global__ void k_prop0(int N) {
    int warp = (blockIdx.x * blockDim.x + threadIdx.x) >> 5;
    int lane = threadIdx.x & 31;
    if (warp >= N) return;
    float ax = 0.0f, ay = 0.0f;
    gather_node((const __half2*)g_w16, g_offs[warp], g_counts[warp], lane, ax, ay);
    ((__half2*)g_l1h)[warp * 32 + lane] = __floats2half2_rn(ax, ay);
}

__global__ void k_prop1(int N) {
    int warp = (blockIdx.x * blockDim.x + threadIdx.x) >> 5;
    int lane = threadIdx.x & 31;
    if (warp >= N) return;
    float ax = 0.0f, ay = 0.0f;
    gather_node((const __half2*)g_l1h, g_offs[warp], g_counts[warp], lane, ax, ay);
    ((__half2*)g_l2h)[warp * 32 + lane] = __floats2half2_rn(ax, ay);
}

// final: acc = 0.25 * (emb0 + l1 + l2 + l3), written once
__global__ void k_prop2(const float2* __restrict__ w2, float2* __restrict__ acc, int N) {
    int warp = (blockIdx.x * blockDim.x + threadIdx.x) >> 5;
    int lane = threadIdx.x & 31;
    if (warp >= N) return;
    float ax = 0.0f, ay = 0.0f;
    gather_node((const __half2*)g_l2h, g_offs[warp], g_counts[warp], lane, ax, ay);
    int idx = warp * 32 + lane;
    float2 e0 = w2[idx];
    float2 l1 = __half22float2(((const __half2*)g_l1h)[idx]);
    float2 l2 = __half22float2(((const __half2*)g_l2h)[idx]);
    acc[idx] = make_float2((e0.x + l1.x + l2.x + ax) * 0.25f,
                           (e0.y + l1.y + l2.y + ay) * 0.25f);
}

// ---------------------------------------------------------------------------
extern "C" void kernel_launch(void* const* d_in, const int* in_sizes, int n_in,
                              void* d_out, int out_size) {
    const void*  edges = d_in[0];                 // [2, E] int32 or int64
    const float* w     = (const float*)d_in[1];   // float32 [N, D]
    int E = in_sizes[0] / 2;
    int N = in_sizes[1] / DIM;
    float* out = (float*)d_out;

    const int TB = 256;
    k_sniff <<<1, 256>>>((const int*)edges);
    k_zero  <<<(N + TB - 1) / TB, TB>>>(N);
    k_count <<<(E + TB - 1) / TB, TB>>>(edges, E, N);
    k_dinv  <<<(N + TB - 1) / TB, TB>>>(N);

    int nb = (N + 1023) / 1024;
    k_scan1<<<nb, 1024>>>(N);
    k_scan2<<<1, 1024>>>(nb);
    k_scan3<<<nb, 1024>>>(N);

    k_scatter<<<(E + TB - 1) / TB, TB>>>(edges, E, N);

    int n4 = N * (DIM / 4);
    k_init<<<(n4 + TB - 1) / TB, TB>>>((const float4*)w, (float4*)out, n4);

    float2* acc = (float2*)(out + (size_t)N * DIM);
    int pgrid = (int)(((long long)N * 32 + TB - 1) / TB);
    k_prop0<<<pgrid, TB>>>(N);
    k_prop1<<<pgrid, TB>>>(N);
    k_prop2<<<pgrid, TB>>>((const float2*)w, acc, N);
}

// round 8
// speedup vs baseline: 1.3793x; 1.1357x over previous
#include <cuda_runtime.h>
#include <cuda_fp16.h>
#include <cuda_bf16.h>

// RecSysGNN (LightGCN, 3 layers) on GB300 — R8.
// - 16-lanes-per-row prop: one LDG.64 serves TWO edges; halves loop iters
// - fused launches (12 -> 9): sniff+zero, dinv+scan1, scan3 folded into users
// - fp16 tables, no-atomic scatter via rank capture, packed 8B CSR entries

#define NMAX 200000
#define EMAX 4000000
#define DIM  64

struct __align__(8) Half4 { __half2 a, b; };

__device__ int      g_is64;
__device__ int      g_counts[NMAX];
__device__ int      g_offs[NMAX];      // block-local exclusive scan (add g_bsums[i>>10])
__device__ float    g_dinv[NMAX];
__device__ int      g_bsums[1024];
__device__ unsigned short g_rank[EMAX];
__device__ __align__(16) long long g_csr[EMAX];   // packed {int src, float norm}
__device__ __align__(16) __half g_w16[(size_t)NMAX * DIM];
__device__ __align__(16) __half g_l1h[(size_t)NMAX * DIM];
__device__ __align__(16) __half g_l2h[(size_t)NMAX * DIM];

// ---------------------------------------------------------------------------
// zero counts; block 0 also sniffs edge dtype (int64 values < 2^31 -> high
// words all zero; uniform int32 values in [0,N) are ~never all zero).
__global__ void k_setup(const int* __restrict__ e, int n) {
    int i = blockIdx.x * blockDim.x + threadIdx.x;
    if (i < n) g_counts[i] = 0;
    if (blockIdx.x == 0) {
        __shared__ int any;
        if (threadIdx.x == 0) any = 0;
        __syncthreads();
        int local = 0;
        for (int j = threadIdx.x; j < 2048; j += blockDim.x)
            if (e[2 * j + 1] != 0) local = 1;
        if (local) any = 1;
        __syncthreads();
        if (threadIdx.x == 0) g_is64 = (any == 0) ? 1 : 0;
    }
}

__device__ __forceinline__ int edge_at(const void* e, size_t idx, int is64) {
    if (is64) return (int)((const long long*)e)[idx];
    return ((const int*)e)[idx];
}

// count + capture per-edge rank within its dst bucket (atomic return value)
__global__ void k_count(const void* __restrict__ edges, int E, int N) {
    int i = blockIdx.x * blockDim.x + threadIdx.x;
    if (i >= E) return;
    int is64 = g_is64;
    int d = edge_at(edges, (size_t)E + i, is64);
    unsigned r = 0;
    if ((unsigned)d < (unsigned)N) r = (unsigned)atomicAdd(&g_counts[d], 1);
    g_rank[i] = (unsigned short)r;
}

__device__ __forceinline__ int warp_iscan(int x, int lane) {
#pragma unroll
    for (int o = 1; o < 32; o <<= 1) {
        int y = __shfl_up_sync(0xffffffffu, x, o);
        if (lane >= o) x += y;
    }
    return x;
}

// block-local exclusive scan of counts -> offs, block sums -> bsums; + dinv
__global__ void k_scan1(int n) {
    int tid  = threadIdx.x;
    int gid  = blockIdx.x * 1024 + tid;
    int v    = (gid < n) ? g_counts[gid] : 0;
    if (gid < n) g_dinv[gid] = (v > 0) ? rsqrtf((float)v) : 0.0f;
    int lane = tid & 31, wid = tid >> 5;
    int inc  = warp_iscan(v, lane);
    __shared__ int ws[32];
    if (lane == 31) ws[wid] = inc;
    __syncthreads();
    if (wid == 0) { int t = ws[lane]; t = warp_iscan(t, lane); ws[lane] = t; }
    __syncthreads();
    int incl = inc + (wid ? ws[wid - 1] : 0);
    if (gid < n) g_offs[gid] = incl - v;
    if (tid == 1023) g_bsums[blockIdx.x] = incl;
}

__global__ void k_scan2(int nb) {
    int tid  = threadIdx.x;
    int v    = (tid < nb) ? g_bsums[tid] : 0;
    int lane = tid & 31, wid = tid >> 5;
    int inc  = warp_iscan(v, lane);
    __shared__ int ws[32];
    if (lane == 31) ws[wid] = inc;
    __syncthreads();
    if (wid == 0) { int t = ws[lane]; t = warp_iscan(t, lane); ws[lane] = t; }
    __syncthreads();
    int incl = inc + (wid ? ws[wid - 1] : 0);
    if (tid < nb) g_bsums[tid] = incl - v;
}

// no atomics: pos = offs[d] + bsums[d>>10] + rank[i]; single packed 8B store
__global__ void k_scatter(const void* __restrict__ edges, int E, int N) {
    int i = blockIdx.x * blockDim.x + threadIdx.x;
    if (i >= E) return;
    int is64 = g_is64;
    int s = edge_at(edges, (size_t)i, is64);
    int d = edge_at(edges, (size_t)E + i, is64);
    if ((unsigned)s >= (unsigned)N || (unsigned)d >= (unsigned)N) return;
    int pos = g_offs[d] + g_bsums[d >> 10] + (int)g_rank[i];
    if ((unsigned)pos < (unsigned)EMAX) {
        float nm = g_dinv[s] * g_dinv[d];
        long long packed = (long long)(unsigned)s |
                           ((long long)(unsigned)__float_as_uint(nm) << 32);
        g_csr[pos] = packed;
    }
}

// out[0:ND) = emb0 copy; also build fp16 copy of w (rows = 16 x Half4)
__global__ void k_init(const float4* __restrict__ w, float4* __restrict__ out, int n4) {
    int i = blockIdx.x * blockDim.x + threadIdx.x;
    if (i < n4) {
        float4 v = w[i];
        out[i] = v;
        Half4 h;
        h.a = __floats2half2_rn(v.x, v.y);
        h.b = __floats2half2_rn(v.z, v.w);
        ((Half4*)g_w16)[i] = h;
    }
}

// One warp per dst node. Lanes 0-15 handle even edges, 16-31 odd edges;
// each lane covers dims [4*sub, 4*sub+4) via one LDG.64 (two edges per iter).
__device__ __forceinline__ void gather2(const uint2* __restrict__ prev,
                                        int start, int cnt, int lane,
                                        float& a0, float& a1, float& a2, float& a3) {
    int sub = lane & 15;
    int h   = lane >> 4;
    for (int b = 0; b < cnt; b += 32) {
        int j = b + lane;
        int s = 0; float nm = 0.0f;
        if (j < cnt) {
            long long p = g_csr[start + j];
            s  = (int)(unsigned)(p & 0xffffffffLL);
            nm = __uint_as_float((unsigned)(p >> 32));
        }
        int m     = min(32, cnt - b);
        int iters = (m + 1) >> 1;
#pragma unroll 4
        for (int k = 0; k < iters; k++) {
            int   srcl = 2 * k + h;                       // zero-padded if OOB
            int   ss = __shfl_sync(0xffffffffu, s,  srcl);
            float nn = __shfl_sync(0xffffffffu, nm, srcl);
            uint2 dv = prev[ss * 16 + sub];
            float2 e0 = __half22float2(*(const __half2*)&dv.x);
            float2 e1 = __half22float2(*(const __half2*)&dv.y);
            a0 = fmaf(nn, e0.x, a0);
            a1 = fmaf(nn, e0.y, a1);
            a2 = fmaf(nn, e1.x, a2);
            a3 = fmaf(nn, e1.y, a3);
        }
    }
    a0 += __shfl_xor_sync(0xffffffffu, a0, 16);
    a1 += __shfl_xor_sync(0xffffffffu, a1, 16);
    a2 += __shfl_xor_sync(0xffffffffu, a2, 16);
    a3 += __shfl_xor_sync(0xffffffffu, a3, 16);
}

__device__ __forceinline__ int node_start(int node) {
    return g_offs[node] + g_bsums[node >> 10];
}

__global__ void k_prop0(int N) {
    int warp = (blockIdx.x * blockDim.x + threadIdx.x) >> 5;
    int lane = threadIdx.x & 31;
    if (warp >= N) return;
    float a0 = 0, a1 = 0, a2 = 0, a3 = 0;
    gather2((const uint2*)g_w16, node_start(warp), g_counts[warp], lane, a0, a1, a2, a3);
    if (lane < 16) {
        Half4 hv;
        hv.a = __floats2half2_rn(a0, a1);
        hv.b = __floats2half2_rn(a2, a3);
        ((Half4*)g_l1h)[warp * 16 + lane] = hv;
    }
}

__global__ void k_prop1(int N) {
    int warp = (blockIdx.x * blockDim.x + threadIdx.x) >> 5;
    int lane = threadIdx.x & 31;
    if (warp >= N) return;
    float a0 = 0, a1 = 0, a2 = 0, a3 = 0;
    gather2((const uint2*)g_l1h, node_start(warp), g_counts[warp], lane, a0, a1, a2, a3);
    if (lane < 16) {
        Half4 hv;
        hv.a = __floats2half2_rn(a0, a1);
        hv.b = __floats2half2_rn(a2, a3);
        ((Half4*)g_l2h)[warp * 16 + lane] = hv;
    }
}

// final: acc = 0.25 * (emb0 + l1 + l2 + l3), written once as float4
__global__ void k_prop2(const float4* __restrict__ w4, float4* __restrict__ acc, int N) {
    int warp = (blockIdx.x * blockDim.x + threadIdx.x) >> 5;
    int lane = threadIdx.x & 31;
    if (warp >= N) return;
    float a0 = 0, a1 = 0, a2 = 0, a3 = 0;
    gather2((const uint2*)g_l2h, node_start(warp), g_counts[warp], lane, a0, a1, a2, a3);
    if (lane < 16) {
        int idx = warp * 16 + lane;
        float4 e0 = w4[idx];
        Half4 h1 = ((const Half4*)g_l1h)[idx];
        Half4 h2 = ((const Half4*)g_l2h)[idx];
        float2 l1a = __half22float2(h1.a), l1b = __half22float2(h1.b);
        float2 l2a = __half22float2(h2.a), l2b = __half22float2(h2.b);
        float4 r;
        r.x = (e0.x + l1a.x + l2a.x + a0) * 0.25f;
        r.y = (e0.y + l1a.y + l2a.y + a1) * 0.25f;
        r.z = (e0.z + l1b.x + l2b.x + a2) * 0.25f;
        r.w = (e0.w + l1b.y + l2b.y + a3) * 0.25f;
        acc[idx] = r;
    }
}

// ---------------------------------------------------------------------------
extern "C" void kernel_launch(void* const* d_in, const int* in_sizes, int n_in,
                              void* d_out, int out_size) {
    const void*  edges = d_in[0];                 // [2, E] int32 or int64
    const float* w     = (const float*)d_in[1];   // float32 [N, D]
    int E = in_sizes[0] / 2;
    int N = in_sizes[1] / DIM;
    float* out = (float*)d_out;

    const int TB = 256;
    k_setup<<<(N + TB - 1) / TB, TB>>>((const int*)edges, N);
    k_count<<<(E + TB - 1) / TB, TB>>>(edges, E, N);

    int nb = (N + 1023) / 1024;
    k_scan1<<<nb, 1024>>>(N);
    k_scan2<<<1, 1024>>>(nb);

    k_scatter<<<(E + TB - 1) / TB, TB>>>(edges, E, N);

    int n4 = N * (DIM / 4);
    k_init<<<(n4 + TB - 1) / TB, TB>>>((const float4*)w, (float4*)out, n4);

    float4* acc = (float4*)(out + (size_t)N * DIM);
    int pgrid = (int)(((long long)N * 32 + TB - 1) / TB);
    k_prop0<<<pgrid, TB>>>(N);
    k_prop1<<<pgrid, TB>>>(N);
    k_prop2<<<pgrid, TB>>>((const float4*)w, acc, N);
}